// round 10
// baseline (speedup 1.0000x reference)
#include <cuda_runtime.h>
#include <cuda_bf16.h>
#include <math.h>

// ---------------- problem constants (validated against in_sizes at runtime) ----
#define MAX_NODES 200000
#define MAX_EDGES 3200000
#define SCAN_B    1024
#define MAX_BLKS  ((MAX_NODES + SCAN_B - 1) / SCAN_B)   // 196

// ---------------- device scratch (static; no allocations allowed) --------------
__device__ int   g_deg[MAX_NODES];
__device__ int   g_rowptr[MAX_NODES + 1];
__device__ int   g_fill[MAX_NODES];
__device__ int   g_bsum[SCAN_B];
__device__ int   g_csr[MAX_EDGES];
__device__ float g_h0[MAX_NODES * 32];
__device__ float g_h1[MAX_NODES * 32];

// ---------------- CSR construction --------------------------------------------
__global__ void k_zero_deg(int* deg, int n) {
    int i = blockIdx.x * blockDim.x + threadIdx.x;
    if (i < n) deg[i] = 0;
}

__global__ void k_hist(const int* __restrict__ dst, int* deg, int E) {
    int e = blockIdx.x * blockDim.x + threadIdx.x;
    if (e < E) atomicAdd(&deg[dst[e]], 1);
}

// per-block inclusive scan -> write block-local exclusive + block totals
__global__ void k_scan1(const int* __restrict__ deg, int* rowptr, int* bsum, int n) {
    __shared__ int sh[SCAN_B];
    int tid = threadIdx.x;
    int i = blockIdx.x * SCAN_B + tid;
    int d = (i < n) ? deg[i] : 0;
    sh[tid] = d;
    __syncthreads();
    int val = d;
    #pragma unroll
    for (int off = 1; off < SCAN_B; off <<= 1) {
        int t = (tid >= off) ? sh[tid - off] : 0;
        __syncthreads();
        val += t;
        sh[tid] = val;
        __syncthreads();
    }
    if (i < n) rowptr[i] = val - d;          // exclusive within block
    if (tid == SCAN_B - 1) bsum[blockIdx.x] = val;
}

// single-block exclusive scan of block sums (nb <= 1024)
__global__ void k_scan2(int* bsum, int nb) {
    __shared__ int sh[SCAN_B];
    int tid = threadIdx.x;
    int d = (tid < nb) ? bsum[tid] : 0;
    sh[tid] = d;
    __syncthreads();
    int val = d;
    #pragma unroll
    for (int off = 1; off < SCAN_B; off <<= 1) {
        int t = (tid >= off) ? sh[tid - off] : 0;
        __syncthreads();
        val += t;
        sh[tid] = val;
        __syncthreads();
    }
    if (tid < nb) bsum[tid] = val - d;       // exclusive
}

__global__ void k_scan3(int* rowptr, const int* __restrict__ bsum, int* fill,
                        int n, int E) {
    int i = blockIdx.x * blockDim.x + threadIdx.x;
    if (i < n) {
        int r = rowptr[i] + bsum[i >> 10];
        rowptr[i] = r;
        fill[i]   = r;
    }
    if (i == 0) rowptr[n] = E;
}

__global__ void k_fill(const int* __restrict__ src, const int* __restrict__ dst,
                       int* fill, int* csr, int E) {
    int e = blockIdx.x * blockDim.x + threadIdx.x;
    if (e < E) {
        int pos = atomicAdd(&fill[dst[e]], 1);
        csr[pos] = src[e];
    }
}

// ---------------- fused SAGE layer: warp per node ------------------------------
// h_out[v] = tanh( h_in[v] @ Ws + mean_neigh(h_in)[v] @ Wn + b )
// Weights live in registers (lane = output column). self/mean broadcast via shfl.
__global__ void __launch_bounds__(256)
k_sage(const float* __restrict__ h_in,
       const float* __restrict__ Ws, const float* __restrict__ Wn,
       const float* __restrict__ b,
       const int* __restrict__ rowptr, const int* __restrict__ csr,
       float* __restrict__ h_out, float* __restrict__ cs_out, int n)
{
    const int lane = threadIdx.x & 31;
    const int gw   = (blockIdx.x * blockDim.x + threadIdx.x) >> 5;
    const int nw   = (gridDim.x * blockDim.x) >> 5;

    float ws[32], wn[32];
    #pragma unroll
    for (int k = 0; k < 32; k++) {
        ws[k] = Ws[k * 32 + lane];
        wn[k] = Wn[k * 32 + lane];
    }
    const float bias = b[lane];

    for (int v = gw; v < n; v += nw) {
        const float self = h_in[v * 32 + lane];
        const int rs = rowptr[v];
        const int re = rowptr[v + 1];

        float a0 = 0.f, a1 = 0.f, a2 = 0.f, a3 = 0.f;
        int e = rs;
        for (; e + 8 <= re; e += 8) {
            int s0 = __ldg(&csr[e + 0]), s1 = __ldg(&csr[e + 1]);
            int s2 = __ldg(&csr[e + 2]), s3 = __ldg(&csr[e + 3]);
            int s4 = __ldg(&csr[e + 4]), s5 = __ldg(&csr[e + 5]);
            int s6 = __ldg(&csr[e + 6]), s7 = __ldg(&csr[e + 7]);
            float v0 = h_in[s0 * 32 + lane], v1 = h_in[s1 * 32 + lane];
            float v2 = h_in[s2 * 32 + lane], v3 = h_in[s3 * 32 + lane];
            float v4 = h_in[s4 * 32 + lane], v5 = h_in[s5 * 32 + lane];
            float v6 = h_in[s6 * 32 + lane], v7 = h_in[s7 * 32 + lane];
            a0 += v0 + v4; a1 += v1 + v5; a2 += v2 + v6; a3 += v3 + v7;
        }
        for (; e < re; e++) {
            int s = __ldg(&csr[e]);
            a0 += h_in[s * 32 + lane];
        }
        const float acc = (a0 + a1) + (a2 + a3);
        const int deg = re - rs;
        const float mean = (deg > 0) ? acc * (1.0f / (float)deg) : 0.0f;

        float out = bias;
        #pragma unroll
        for (int k = 0; k < 32; k++) {
            float sk = __shfl_sync(0xffffffffu, self, k);
            float mk = __shfl_sync(0xffffffffu, mean, k);
            out = fmaf(sk, ws[k], fmaf(mk, wn[k], out));
        }
        const float t = tanhf(out);
        h_out[v * 32 + lane]   = t;
        cs_out[v * 128 + lane] = t;   // caller pre-offsets by 32*layer
    }
}

// ---------------- pair MLP: 8 pairs per block, W1 in shared --------------------
#define PPB 8
__global__ void __launch_bounds__(128)
k_pair(const float* __restrict__ cs, const int* __restrict__ uidx,
       const int* __restrict__ iidx,
       const float* __restrict__ W1, const float* __restrict__ bl1,
       const float* __restrict__ W2, const float* __restrict__ bl2,
       float* __restrict__ score, int n_pairs)
{
    extern __shared__ float sh[];
    float* sW1 = sh;                 // 256*128
    float* sPT = sW1 + 256 * 128;    // [256][PPB]  (k-major, 8 floats/row = 32B)
    float* sH  = sPT + 256 * PPB;    // [PPB][128]

    const int tid  = threadIdx.x;    // 128 threads
    const int warp = tid >> 5;
    const int lane = tid & 31;

    for (int i = tid; i < 256 * 128; i += 128) sW1[i] = W1[i];
    const float b1 = bl1[tid];
    const float w2 = W2[tid];
    const float b2 = bl2[0];

    const int pbase = blockIdx.x * PPB;
    #pragma unroll
    for (int p = 0; p < PPB; p++) {
        int pr = pbase + p;
        int safe = (pr < n_pairs) ? pr : 0;
        int u = uidx[safe];
        int it = iidx[safe];
        sPT[tid * PPB + p]         = cs[u  * 128 + tid];
        sPT[(128 + tid) * PPB + p] = cs[it * 128 + tid];
    }
    __syncthreads();

    float acc[PPB];
    #pragma unroll
    for (int p = 0; p < PPB; p++) acc[p] = b1;

    #pragma unroll 4
    for (int k = 0; k < 256; k++) {
        float w = sW1[k * 128 + tid];                       // conflict-free
        float4 pa = *reinterpret_cast<const float4*>(&sPT[k * PPB]);     // broadcast
        float4 pb = *reinterpret_cast<const float4*>(&sPT[k * PPB + 4]); // broadcast
        acc[0] = fmaf(pa.x, w, acc[0]);
        acc[1] = fmaf(pa.y, w, acc[1]);
        acc[2] = fmaf(pa.z, w, acc[2]);
        acc[3] = fmaf(pa.w, w, acc[3]);
        acc[4] = fmaf(pb.x, w, acc[4]);
        acc[5] = fmaf(pb.y, w, acc[5]);
        acc[6] = fmaf(pb.z, w, acc[6]);
        acc[7] = fmaf(pb.w, w, acc[7]);
    }

    #pragma unroll
    for (int p = 0; p < PPB; p++)
        sH[p * 128 + tid] = fmaxf(acc[p], 0.0f) * w2;       // hdn * W2 column-wise
    __syncthreads();

    for (int p = warp; p < PPB; p += 4) {
        float v = sH[p * 128 + lane] + sH[p * 128 + 32 + lane]
                + sH[p * 128 + 64 + lane] + sH[p * 128 + 96 + lane];
        #pragma unroll
        for (int o = 16; o > 0; o >>= 1) v += __shfl_down_sync(0xffffffffu, v, o);
        if (lane == 0 && (pbase + p) < n_pairs)
            score[pbase + p] = 1.0f / (1.0f + expf(-(v + b2)));
    }
}

// ---------------- launch --------------------------------------------------------
extern "C" void kernel_launch(void* const* d_in, const int* in_sizes, int n_in,
                              void* d_out, int out_size)
{
    const float* x        = (const float*)d_in[0];
    const int*   src      = (const int*)  d_in[1];
    const int*   dst      = (const int*)  d_in[2];
    const int*   user_idx = (const int*)  d_in[3];
    const int*   item_idx = (const int*)  d_in[4];
    const float* Wsx[4] = { (const float*)d_in[5],  (const float*)d_in[8],
                            (const float*)d_in[11], (const float*)d_in[14] };
    const float* Wnx[4] = { (const float*)d_in[6],  (const float*)d_in[9],
                            (const float*)d_in[12], (const float*)d_in[15] };
    const float* bx[4]  = { (const float*)d_in[7],  (const float*)d_in[10],
                            (const float*)d_in[13], (const float*)d_in[16] };
    const float* W1  = (const float*)d_in[17];
    const float* bl1 = (const float*)d_in[18];
    const float* W2  = (const float*)d_in[19];
    const float* bl2 = (const float*)d_in[20];

    const int N = in_sizes[0] / 32;
    const int E = in_sizes[1];
    const int P = in_sizes[3];

    float* out   = (float*)d_out;
    float* score = out;                 // [P]
    float* cs    = out + P;             // [N,128] concat_states

    void *p_deg, *p_rowptr, *p_fill, *p_bsum, *p_csr, *p_h0, *p_h1;
    cudaGetSymbolAddress(&p_deg,    g_deg);
    cudaGetSymbolAddress(&p_rowptr, g_rowptr);
    cudaGetSymbolAddress(&p_fill,   g_fill);
    cudaGetSymbolAddress(&p_bsum,   g_bsum);
    cudaGetSymbolAddress(&p_csr,    g_csr);
    cudaGetSymbolAddress(&p_h0,     g_h0);
    cudaGetSymbolAddress(&p_h1,     g_h1);
    int*   deg    = (int*)p_deg;
    int*   rowptr = (int*)p_rowptr;
    int*   fill   = (int*)p_fill;
    int*   bsum   = (int*)p_bsum;
    int*   csr    = (int*)p_csr;
    float* h0     = (float*)p_h0;
    float* h1     = (float*)p_h1;

    // --- CSR build ---
    k_zero_deg<<<(N + 255) / 256, 256>>>(deg, N);
    k_hist<<<(E + 255) / 256, 256>>>(dst, deg, E);
    const int nb = (N + SCAN_B - 1) / SCAN_B;
    k_scan1<<<nb, SCAN_B>>>(deg, rowptr, bsum, N);
    k_scan2<<<1, SCAN_B>>>(bsum, nb);
    k_scan3<<<(N + 255) / 256, 256>>>(rowptr, bsum, fill, N, E);
    k_fill<<<(E + 255) / 256, 256>>>(src, dst, fill, csr, E);

    // --- 4 SAGE layers (fused gather + GEMV + tanh), ping-pong h buffers ---
    const int sage_blocks = 148 * 8;
    const float* hin = x;
    float* bufs[2] = { h0, h1 };
    for (int l = 0; l < 4; l++) {
        float* hout = bufs[l & 1];
        k_sage<<<sage_blocks, 256>>>(hin, Wsx[l], Wnx[l], bx[l],
                                     rowptr, csr, hout, cs + 32 * l, N);
        hin = hout;
    }

    // --- pair MLP ---
    const int smem = (256 * 128 + 256 * PPB + PPB * 128) * (int)sizeof(float);
    cudaFuncSetAttribute(k_pair, cudaFuncAttributeMaxDynamicSharedMemorySize, smem);
    k_pair<<<(P + PPB - 1) / PPB, 128, smem>>>(cs, user_idx, item_idx,
                                               W1, bl1, W2, bl2, score, P);
}

// round 11
// speedup vs baseline: 1.2589x; 1.2589x over previous
#include <cuda_runtime.h>
#include <cuda_bf16.h>
#include <math.h>

// ---------------- problem constants ----------------
#define MAX_NODES 200000
#define MAX_EDGES 3200000
#define SCAN_B    1024
#define TILE      256
#define PADR      33     // smem row pad (conflict-free column reads)

// ---------------- device scratch (no allocations allowed) --------------
__device__ int g_deg[MAX_NODES];
__device__ int g_rowptr[MAX_NODES + 1];
__device__ int g_fill[MAX_NODES];
__device__ int g_bsum[SCAN_B];
__device__ int g_csr[MAX_EDGES];

// ---------------- CSR construction ----------------
__global__ void k_zero_deg(int* deg, int n) {
    int i = blockIdx.x * blockDim.x + threadIdx.x;
    if (i < n) deg[i] = 0;
}

__global__ void k_hist(const int* __restrict__ dst, int* deg, int E) {
    int e = blockIdx.x * blockDim.x + threadIdx.x;
    if (e < E) atomicAdd(&deg[dst[e]], 1);
}

__global__ void k_scan1(const int* __restrict__ deg, int* rowptr, int* bsum, int n) {
    __shared__ int sh[SCAN_B];
    int tid = threadIdx.x;
    int i = blockIdx.x * SCAN_B + tid;
    int d = (i < n) ? deg[i] : 0;
    sh[tid] = d;
    __syncthreads();
    int val = d;
    #pragma unroll
    for (int off = 1; off < SCAN_B; off <<= 1) {
        int t = (tid >= off) ? sh[tid - off] : 0;
        __syncthreads();
        val += t;
        sh[tid] = val;
        __syncthreads();
    }
    if (i < n) rowptr[i] = val - d;
    if (tid == SCAN_B - 1) bsum[blockIdx.x] = val;
}

__global__ void k_scan2(int* bsum, int nb) {
    __shared__ int sh[SCAN_B];
    int tid = threadIdx.x;
    int d = (tid < nb) ? bsum[tid] : 0;
    sh[tid] = d;
    __syncthreads();
    int val = d;
    #pragma unroll
    for (int off = 1; off < SCAN_B; off <<= 1) {
        int t = (tid >= off) ? sh[tid - off] : 0;
        __syncthreads();
        val += t;
        sh[tid] = val;
        __syncthreads();
    }
    if (tid < nb) bsum[tid] = val - d;
}

__global__ void k_scan3(int* rowptr, const int* __restrict__ bsum, int* fill,
                        int n, int E) {
    int i = blockIdx.x * blockDim.x + threadIdx.x;
    if (i < n) {
        int r = rowptr[i] + bsum[i >> 10];
        rowptr[i] = r;
        fill[i]   = r;
    }
    if (i == 0) rowptr[n] = E;
}

__global__ void k_fill(const int* __restrict__ src, const int* __restrict__ dst,
                       int* fill, int* csr, int E) {
    int e = blockIdx.x * blockDim.x + threadIdx.x;
    if (e < E) {
        int pos = atomicAdd(&fill[dst[e]], 1);
        csr[pos] = src[e];
    }
}

// ---------------- fused SAGE layer ----------------
// Phase A: warp-per-node mean gather (predicated, no serial tail) -> smem stage
// Phase B: thread-per-node dense GEMV out = tanh([self;mean] @ [Ws;Wn] + b)
//          weights in smem (uniform LDS.128 broadcast), acc[32] in registers.
// Input rows read with 'stride' (32 for x, 128 for cs slices); output written
// directly into the node's concat_states slice (row stride 128 floats).
__global__ void __launch_bounds__(TILE)
k_sage(const float* __restrict__ h_in, int stride,
       const float* __restrict__ Ws, const float* __restrict__ Wn,
       const float* __restrict__ bias,
       const int* __restrict__ rowptr, const int* __restrict__ csr,
       float* __restrict__ cs_out, int n)
{
    __shared__ float sW[2048];            // [64 k][32 j]: Ws rows then Wn rows
    __shared__ float sB[32];
    __shared__ float sM[TILE * PADR];     // staged means, padded rows

    const int tid  = threadIdx.x;
    const int lane = tid & 31;
    const int wid  = tid >> 5;
    const int base = blockIdx.x * TILE;

    for (int i = tid; i < 1024; i += TILE) {
        sW[i]        = Ws[i];
        sW[1024 + i] = Wn[i];
    }
    if (tid < 32) sB[tid] = bias[tid];
    __syncthreads();

    // ---- Phase A: gather means for this warp's 32 nodes ----
    #pragma unroll 1
    for (int i = 0; i < 32; i++) {
        const int v = base + wid * 32 + i;
        float mean = 0.0f;
        if (v < n) {
            const int rs = __ldg(&rowptr[v]);
            const int re = __ldg(&rowptr[v + 1]);
            float a0 = 0.f, a1 = 0.f, a2 = 0.f, a3 = 0.f;
            float a4 = 0.f, a5 = 0.f, a6 = 0.f, a7 = 0.f;
            #pragma unroll 1
            for (int e = rs; e < re; e += 8) {
                bool p0 = true,        p1 = (e + 1 < re), p2 = (e + 2 < re), p3 = (e + 3 < re);
                bool p4 = (e + 4 < re), p5 = (e + 5 < re), p6 = (e + 6 < re), p7 = (e + 7 < re);
                int s0 =       __ldg(&csr[e + 0]);
                int s1 = p1 ? __ldg(&csr[e + 1]) : 0;
                int s2 = p2 ? __ldg(&csr[e + 2]) : 0;
                int s3 = p3 ? __ldg(&csr[e + 3]) : 0;
                int s4 = p4 ? __ldg(&csr[e + 4]) : 0;
                int s5 = p5 ? __ldg(&csr[e + 5]) : 0;
                int s6 = p6 ? __ldg(&csr[e + 6]) : 0;
                int s7 = p7 ? __ldg(&csr[e + 7]) : 0;
                float f0 =       __ldg(&h_in[s0 * stride + lane]);
                float f1 = p1 ? __ldg(&h_in[s1 * stride + lane]) : 0.f;
                float f2 = p2 ? __ldg(&h_in[s2 * stride + lane]) : 0.f;
                float f3 = p3 ? __ldg(&h_in[s3 * stride + lane]) : 0.f;
                float f4 = p4 ? __ldg(&h_in[s4 * stride + lane]) : 0.f;
                float f5 = p5 ? __ldg(&h_in[s5 * stride + lane]) : 0.f;
                float f6 = p6 ? __ldg(&h_in[s6 * stride + lane]) : 0.f;
                float f7 = p7 ? __ldg(&h_in[s7 * stride + lane]) : 0.f;
                a0 += f0; a1 += f1; a2 += f2; a3 += f3;
                a4 += f4; a5 += f5; a6 += f6; a7 += f7;
            }
            const float acc = ((a0 + a1) + (a2 + a3)) + ((a4 + a5) + (a6 + a7));
            const int deg = re - rs;
            mean = (deg > 0) ? acc * (1.0f / (float)deg) : 0.0f;
        }
        sM[(wid * 32 + i) * PADR + lane] = mean;
    }
    __syncwarp();

    // ---- Phase B: thread-per-node dense transform ----
    const int v = base + tid;
    if (v >= n) return;

    float vs[32];
    const float4* selfp = reinterpret_cast<const float4*>(h_in + v * stride);
    #pragma unroll
    for (int q = 0; q < 8; q++) {
        float4 t = __ldg(&selfp[q]);
        vs[4 * q + 0] = t.x; vs[4 * q + 1] = t.y;
        vs[4 * q + 2] = t.z; vs[4 * q + 3] = t.w;
    }

    float acc[32];
    #pragma unroll
    for (int j = 0; j < 32; j++) acc[j] = sB[j];

    const float4* sW4 = reinterpret_cast<const float4*>(sW);

    // self @ Ws  (k fully unrolled: vs[] stays in registers)
    #pragma unroll
    for (int k = 0; k < 32; k++) {
        const float vk = vs[k];
        #pragma unroll
        for (int q = 0; q < 8; q++) {
            float4 w = sW4[k * 8 + q];
            acc[4 * q + 0] = fmaf(vk, w.x, acc[4 * q + 0]);
            acc[4 * q + 1] = fmaf(vk, w.y, acc[4 * q + 1]);
            acc[4 * q + 2] = fmaf(vk, w.z, acc[4 * q + 2]);
            acc[4 * q + 3] = fmaf(vk, w.w, acc[4 * q + 3]);
        }
    }

    // mean @ Wn  (vk from conflict-free smem row; loop stays rolled)
    const float* myrow = &sM[tid * PADR];
    #pragma unroll 4
    for (int k = 0; k < 32; k++) {
        const float vk = myrow[k];
        #pragma unroll
        for (int q = 0; q < 8; q++) {
            float4 w = sW4[(32 + k) * 8 + q];
            acc[4 * q + 0] = fmaf(vk, w.x, acc[4 * q + 0]);
            acc[4 * q + 1] = fmaf(vk, w.y, acc[4 * q + 1]);
            acc[4 * q + 2] = fmaf(vk, w.z, acc[4 * q + 2]);
            acc[4 * q + 3] = fmaf(vk, w.w, acc[4 * q + 3]);
        }
    }

    float4* outp = reinterpret_cast<float4*>(cs_out + v * 128);
    #pragma unroll
    for (int q = 0; q < 8; q++) {
        float4 o;
        o.x = tanhf(acc[4 * q + 0]);
        o.y = tanhf(acc[4 * q + 1]);
        o.z = tanhf(acc[4 * q + 2]);
        o.w = tanhf(acc[4 * q + 3]);
        outp[q] = o;
    }
}

// ---------------- pair MLP: 8 pairs per block, W1 in shared --------------------
#define PPB 8
__global__ void __launch_bounds__(128)
k_pair(const float* __restrict__ cs, const int* __restrict__ uidx,
       const int* __restrict__ iidx,
       const float* __restrict__ W1, const float* __restrict__ bl1,
       const float* __restrict__ W2, const float* __restrict__ bl2,
       float* __restrict__ score, int n_pairs)
{
    extern __shared__ float sh[];
    float* sW1 = sh;                 // 256*128
    float* sPT = sW1 + 256 * 128;    // [256][PPB]
    float* sH  = sPT + 256 * PPB;    // [PPB][128]

    const int tid  = threadIdx.x;
    const int warp = tid >> 5;
    const int lane = tid & 31;

    for (int i = tid; i < 256 * 128; i += 128) sW1[i] = W1[i];
    const float b1 = bl1[tid];
    const float w2 = W2[tid];
    const float b2 = bl2[0];

    const int pbase = blockIdx.x * PPB;
    #pragma unroll
    for (int p = 0; p < PPB; p++) {
        int pr = pbase + p;
        int safe = (pr < n_pairs) ? pr : 0;
        int u  = uidx[safe];
        int it = iidx[safe];
        sPT[tid * PPB + p]         = cs[u  * 128 + tid];
        sPT[(128 + tid) * PPB + p] = cs[it * 128 + tid];
    }
    __syncthreads();

    float acc[PPB];
    #pragma unroll
    for (int p = 0; p < PPB; p++) acc[p] = b1;

    #pragma unroll 4
    for (int k = 0; k < 256; k++) {
        float w = sW1[k * 128 + tid];
        float4 pa = *reinterpret_cast<const float4*>(&sPT[k * PPB]);
        float4 pb = *reinterpret_cast<const float4*>(&sPT[k * PPB + 4]);
        acc[0] = fmaf(pa.x, w, acc[0]);
        acc[1] = fmaf(pa.y, w, acc[1]);
        acc[2] = fmaf(pa.z, w, acc[2]);
        acc[3] = fmaf(pa.w, w, acc[3]);
        acc[4] = fmaf(pb.x, w, acc[4]);
        acc[5] = fmaf(pb.y, w, acc[5]);
        acc[6] = fmaf(pb.z, w, acc[6]);
        acc[7] = fmaf(pb.w, w, acc[7]);
    }

    #pragma unroll
    for (int p = 0; p < PPB; p++)
        sH[p * 128 + tid] = fmaxf(acc[p], 0.0f) * w2;
    __syncthreads();

    for (int p = warp; p < PPB; p += 4) {
        float v = sH[p * 128 + lane] + sH[p * 128 + 32 + lane]
                + sH[p * 128 + 64 + lane] + sH[p * 128 + 96 + lane];
        #pragma unroll
        for (int o = 16; o > 0; o >>= 1) v += __shfl_down_sync(0xffffffffu, v, o);
        if (lane == 0 && (pbase + p) < n_pairs)
            score[pbase + p] = 1.0f / (1.0f + expf(-(v + b2)));
    }
}

// ---------------- launch ----------------
extern "C" void kernel_launch(void* const* d_in, const int* in_sizes, int n_in,
                              void* d_out, int out_size)
{
    const float* x        = (const float*)d_in[0];
    const int*   src      = (const int*)  d_in[1];
    const int*   dst      = (const int*)  d_in[2];
    const int*   user_idx = (const int*)  d_in[3];
    const int*   item_idx = (const int*)  d_in[4];
    const float* Wsx[4] = { (const float*)d_in[5],  (const float*)d_in[8],
                            (const float*)d_in[11], (const float*)d_in[14] };
    const float* Wnx[4] = { (const float*)d_in[6],  (const float*)d_in[9],
                            (const float*)d_in[12], (const float*)d_in[15] };
    const float* bx[4]  = { (const float*)d_in[7],  (const float*)d_in[10],
                            (const float*)d_in[13], (const float*)d_in[16] };
    const float* W1  = (const float*)d_in[17];
    const float* bl1 = (const float*)d_in[18];
    const float* W2  = (const float*)d_in[19];
    const float* bl2 = (const float*)d_in[20];

    const int N = in_sizes[0] / 32;
    const int E = in_sizes[1];
    const int P = in_sizes[3];

    float* out   = (float*)d_out;
    float* score = out;                 // [P]
    float* cs    = out + P;             // [N,128] concat_states

    void *p_deg, *p_rowptr, *p_fill, *p_bsum, *p_csr;
    cudaGetSymbolAddress(&p_deg,    g_deg);
    cudaGetSymbolAddress(&p_rowptr, g_rowptr);
    cudaGetSymbolAddress(&p_fill,   g_fill);
    cudaGetSymbolAddress(&p_bsum,   g_bsum);
    cudaGetSymbolAddress(&p_csr,    g_csr);
    int* deg    = (int*)p_deg;
    int* rowptr = (int*)p_rowptr;
    int* fill   = (int*)p_fill;
    int* bsum   = (int*)p_bsum;
    int* csr    = (int*)p_csr;

    // --- CSR build ---
    k_zero_deg<<<(N + 255) / 256, 256>>>(deg, N);
    k_hist<<<(E + 255) / 256, 256>>>(dst, deg, E);
    const int nb = (N + SCAN_B - 1) / SCAN_B;
    k_scan1<<<nb, SCAN_B>>>(deg, rowptr, bsum, N);
    k_scan2<<<1, SCAN_B>>>(bsum, nb);
    k_scan3<<<(N + 255) / 256, 256>>>(rowptr, bsum, fill, N, E);
    k_fill<<<(E + 255) / 256, 256>>>(src, dst, fill, csr, E);

    // --- 4 SAGE layers, writing straight into concat_states slices ---
    const int sage_grid = (N + TILE - 1) / TILE;
    k_sage<<<sage_grid, TILE>>>(x, 32, Wsx[0], Wnx[0], bx[0],
                                rowptr, csr, cs + 0, N);
    for (int l = 1; l < 4; l++) {
        k_sage<<<sage_grid, TILE>>>(cs + 32 * (l - 1), 128,
                                    Wsx[l], Wnx[l], bx[l],
                                    rowptr, csr, cs + 32 * l, N);
    }

    // --- pair MLP ---
    const int smem = (256 * 128 + 256 * PPB + PPB * 128) * (int)sizeof(float);
    cudaFuncSetAttribute(k_pair, cudaFuncAttributeMaxDynamicSharedMemorySize, smem);
    k_pair<<<(P + PPB - 1) / PPB, 128, smem>>>(cs, user_idx, item_idx,
                                               W1, bl1, W2, bl2, score, P);
}